// round 6
// baseline (speedup 1.0000x reference)
#include <cuda_runtime.h>
#include <cuda_bf16.h>

// Elementwise hard clip: out[i] = clamp(x[i], -0.5f, 0.5f)
// N = 67,108,864 fp32. One resident wave: 444 CTAs (3/SM x 148 SMs),
// each streaming one ~590KB contiguous tile with 16-deep front-batched
// 128-bit loads then 16 stores (64KB R / 64KB W bursts per CTA).

#define CLIP_LO (-0.5f)
#define CLIP_HI (0.5f)
#define BATCH 16

__device__ __forceinline__ float4 clip4(float4 v) {
    v.x = fminf(fmaxf(v.x, CLIP_LO), CLIP_HI);
    v.y = fminf(fmaxf(v.y, CLIP_LO), CLIP_HI);
    v.z = fminf(fmaxf(v.z, CLIP_LO), CLIP_HI);
    v.w = fminf(fmaxf(v.w, CLIP_LO), CLIP_HI);
    return v;
}

__global__ __launch_bounds__(256) void clip_kernel_wave(
    const float4* __restrict__ in, float4* __restrict__ out,
    int n4, int chunk)
{
    const int bdim = blockDim.x;
    int start = blockIdx.x * chunk;
    int end = start + chunk;
    if (end > n4) end = n4;

    int i = start + threadIdx.x;
    const int step = bdim * BATCH;

    for (; i + (BATCH - 1) * bdim < end; i += step) {
        float4 v[BATCH];
#pragma unroll
        for (int j = 0; j < BATCH; j++)
            v[j] = __ldcs(in + i + j * bdim);
#pragma unroll
        for (int j = 0; j < BATCH; j++)
            v[j] = clip4(v[j]);
#pragma unroll
        for (int j = 0; j < BATCH; j++)
            __stcs(out + i + j * bdim, v[j]);
    }
    // Remainder within the tile (sub-BATCH iterations)
    for (; i < end; i += bdim) {
        float4 a = __ldcs(in + i);
        __stcs(out + i, clip4(a));
    }
}

// Scalar tail for N not divisible by 4 (not hit for this problem's N).
__global__ void clip_kernel_tail(
    const float* __restrict__ in, float* __restrict__ out, int start, int n)
{
    int i = start + blockIdx.x * blockDim.x + threadIdx.x;
    if (i < n) {
        out[i] = fminf(fmaxf(__ldcs(in + i), CLIP_LO), CLIP_HI);
    }
}

extern "C" void kernel_launch(void* const* d_in, const int* in_sizes, int n_in,
                              void* d_out, int out_size)
{
    const float* x = (const float*)d_in[0];
    float* out = (float*)d_out;
    int n = in_sizes[0];

    int n4 = n / 4;
    const int threads = 256;

    // One resident wave: regs=80 -> 3 CTAs/SM, 148 SMs -> 444 CTAs.
    // Each CTA gets one contiguous chunk (rounded to a warp-aligned multiple
    // of blockDim so the batched loop stays coalesced).
    int blocks = 148 * 3;
    int chunk = (n4 + blocks - 1) / blocks;
    chunk = ((chunk + threads - 1) / threads) * threads;
    blocks = (n4 + chunk - 1) / chunk;
    if (blocks < 1) { blocks = 1; chunk = n4 > 0 ? n4 : 1; }

    clip_kernel_wave<<<blocks, threads>>>(
        (const float4*)x, (float4*)out, n4, chunk);

    int tail_start = n4 * 4;
    int tail = n - tail_start;
    if (tail > 0) {
        clip_kernel_tail<<<(tail + 255) / 256, 256>>>(x, out, tail_start, n);
    }
}

// round 7
// speedup vs baseline: 1.1363x; 1.1363x over previous
#include <cuda_runtime.h>
#include <cuda_bf16.h>
#include <cstdint>

// Elementwise hard clip: out[i] = clamp(x[i], -0.5f, 0.5f)
// N = 67,108,864 fp32. Contiguous 128KB per-CTA tiles, 8-deep front-batched
// 256-bit (v8.f32) streaming loads, then 8 256-bit stores.
// Geometry = R5 best (2048 CTAs, 256 threads); access width is the only change.

#define CLIP_LO (-0.5f)
#define CLIP_HI (0.5f)
#define BATCH 8   // 8 x 32B = 256B per thread per iteration (64KB burst per CTA)

struct f8 { float v[8]; };

__device__ __forceinline__ f8 ld256cs(const float* p) {
    f8 r;
    asm volatile(
        "ld.global.cs.v8.f32 {%0,%1,%2,%3,%4,%5,%6,%7}, [%8];"
        : "=f"(r.v[0]), "=f"(r.v[1]), "=f"(r.v[2]), "=f"(r.v[3]),
          "=f"(r.v[4]), "=f"(r.v[5]), "=f"(r.v[6]), "=f"(r.v[7])
        : "l"(p));
    return r;
}

__device__ __forceinline__ void st256cs(float* p, const f8& r) {
    asm volatile(
        "st.global.cs.v8.f32 [%0], {%1,%2,%3,%4,%5,%6,%7,%8};"
        :: "l"(p),
           "f"(r.v[0]), "f"(r.v[1]), "f"(r.v[2]), "f"(r.v[3]),
           "f"(r.v[4]), "f"(r.v[5]), "f"(r.v[6]), "f"(r.v[7])
        : "memory");
}

__device__ __forceinline__ void clip8(f8& a) {
#pragma unroll
    for (int k = 0; k < 8; k++)
        a.v[k] = fminf(fmaxf(a.v[k], CLIP_LO), CLIP_HI);
}

// Each CTA owns a contiguous tile [start, start+chunk) in float8 (32B) units.
// Per iteration: BATCH independent 256-bit loads (64KB/CTA read burst), clip,
// then BATCH 256-bit stores (64KB/CTA write burst).
__global__ __launch_bounds__(256) void clip_kernel_v8wide(
    const float* __restrict__ in, float* __restrict__ out,
    int n8, int chunk)
{
    const int bdim = blockDim.x;
    int start = blockIdx.x * chunk;
    int end = start + chunk;
    if (end > n8) end = n8;

    int i = start + threadIdx.x;
    const int step = bdim * BATCH;

    for (; i + (BATCH - 1) * bdim < end; i += step) {
        f8 v[BATCH];
#pragma unroll
        for (int j = 0; j < BATCH; j++)
            v[j] = ld256cs(in + (size_t)(i + j * bdim) * 8);
#pragma unroll
        for (int j = 0; j < BATCH; j++)
            clip8(v[j]);
#pragma unroll
        for (int j = 0; j < BATCH; j++)
            st256cs(out + (size_t)(i + j * bdim) * 8, v[j]);
    }
    // Remainder within the tile (sub-BATCH iterations)
    for (; i < end; i += bdim) {
        f8 a = ld256cs(in + (size_t)i * 8);
        clip8(a);
        st256cs(out + (size_t)i * 8, a);
    }
}

// Scalar tail for N not divisible by 8 (not hit for this problem's N).
__global__ void clip_kernel_tail(
    const float* __restrict__ in, float* __restrict__ out, int start, int n)
{
    int i = start + blockIdx.x * blockDim.x + threadIdx.x;
    if (i < n) {
        out[i] = fminf(fmaxf(__ldcs(in + i), CLIP_LO), CLIP_HI);
    }
}

extern "C" void kernel_launch(void* const* d_in, const int* in_sizes, int n_in,
                              void* d_out, int out_size)
{
    const float* x = (const float*)d_in[0];
    float* out = (float*)d_out;
    int n = in_sizes[0];

    int n8 = n / 8;
    const int threads = 256;

    // 2048 CTAs: for n8 = 2^23, chunk = 4096 float8 = 128KB contiguous per CTA
    // (2 batched iterations of 64KB each). Same geometry as the best round.
    int blocks = 2048;
    int chunk = (n8 + blocks - 1) / blocks;
    chunk = ((chunk + threads - 1) / threads) * threads;
    blocks = (n8 + chunk - 1) / chunk;
    if (blocks < 1) { blocks = 1; chunk = n8 > 0 ? n8 : 1; }

    clip_kernel_v8wide<<<blocks, threads>>>(x, out, n8, chunk);

    int tail_start = n8 * 8;
    int tail = n - tail_start;
    if (tail > 0) {
        clip_kernel_tail<<<(tail + 255) / 256, 256>>>(x, out, tail_start, n);
    }
}